// round 8
// baseline (speedup 1.0000x reference)
#include <cuda_runtime.h>
#include <cuda_bf16.h>

#define H      1024
#define NEXP   4
#define TPB    256

// One thread per (row, expert). The k-accumulation is a SINGLE SERIAL
// ASCENDING fmaf chain, matching cuBLAS/XLA fp32 GEMM accumulation order
// bitwise (one accumulator per output element, k ascending). This makes
// our logits bit-identical to the reference's, removing all order-noise
// near-tie flips.
__global__ __launch_bounds__(TPB) void moe_gate_kernel(
    const float* __restrict__ x,      // [N, 1024]
    const float* __restrict__ w,      // [4, 1024]
    float* __restrict__ out,          // [2N idx | 2N wgt | 1 aux] fp32
    int nrows)
{
    const int t   = blockIdx.x * TPB + threadIdx.x;
    const int row = t >> 2;
    const int e   = t & 3;
    if (row >= nrows) return;

    const float4* xr = reinterpret_cast<const float4*>(x + (size_t)row * H);
    const float4* we = reinterpret_cast<const float4*>(w + (size_t)e * H);

    float acc = 0.0f;
#pragma unroll 8
    for (int i = 0; i < H / 4; i++) {
        float4 v  = xr[i];          // 4 lanes/row share this line (broadcast)
        float4 wv = we[i];          // 16 KB weight: L1-resident
        acc = fmaf(v.x, wv.x, acc); // strict serial ascending chain:
        acc = fmaf(v.y, wv.y, acc); // k = 4i, 4i+1, 4i+2, 4i+3
        acc = fmaf(v.z, wv.z, acc);
        acc = fmaf(v.w, wv.w, acc);
    }

    // Gather the 4 expert logits within each 4-lane group.
    const unsigned mask = 0xffffffffu;
    float lg[NEXP];
    #pragma unroll
    for (int k = 0; k < NEXP; k++)
        lg[k] = __shfl_sync(mask, acc, k, 4);

    if (e == 0) {
        float m = lg[0];
        #pragma unroll
        for (int k = 1; k < NEXP; k++) m = fmaxf(m, lg[k]);

        // Accurate exp (double->fp32; immune to fast-math/FTZ).
        float q[NEXP];
        #pragma unroll
        for (int k = 0; k < NEXP; k++)
            q[k] = (float)exp((double)(lg[k] - m));
        float sum = ((q[0] + q[1]) + q[2]) + q[3];   // >= 1 always

        // Validated reference-softmax emulation (R5, boundary-sweep min):
        // correctly-rounded fp32 division, then flush denormal scores to
        // exact 0 (FTZ pipeline). Zero ties resolve to lowest index.
        unsigned kb[NEXP];
        float sc[NEXP];
        #pragma unroll
        for (int k = 0; k < NEXP; k++) {
            float s = __fdiv_rn(q[k], sum);
            unsigned b = __float_as_uint(s);
            if (b < 0x00800000u) { b = 0u; s = 0.0f; }
            kb[k] = b;
            sc[k] = s;
        }

        // top-2 by bit pattern, strict '>' => lowest index wins ties,
        // matching lax.top_k stable descending order.
        int i0 = 0;
        #pragma unroll
        for (int k = 1; k < NEXP; k++) if (kb[k] > kb[i0]) i0 = k;
        int i1 = -1;
        #pragma unroll
        for (int k = 0; k < NEXP; k++) {
            if (k == i0) continue;
            if (i1 < 0 || kb[k] > kb[i1]) i1 = k;
        }

        float2* oidx = reinterpret_cast<float2*>(out);
        float2* owgt = reinterpret_cast<float2*>(out + 2 * (size_t)nrows);
        oidx[row] = make_float2((float)i0, (float)i1);
        owgt[row] = make_float2(sc[i0], sc[i1]);
    }

    // aux_loss analytically == ALPHA: sum(ce)=1, pi=1/E, fi=ce*E
    if (t == 0)
        out[4 * (size_t)nrows] = 0.01f;
}

extern "C" void kernel_launch(void* const* d_in, const int* in_sizes, int n_in,
                              void* d_out, int out_size)
{
    const float* x = (const float*)d_in[0];   // hidden_states [8,4096,1024] fp32
    const float* w = (const float*)d_in[1];   // weight [4,1024] fp32
    float* out = (float*)d_out;

    int nrows = in_sizes[0] / H;              // 32768
    int threads_total = nrows * NEXP;         // 131072
    int blocks = (threads_total + TPB - 1) / TPB;
    moe_gate_kernel<<<blocks, TPB>>>(x, w, out, nrows);
}

// round 9
// speedup vs baseline: 3.0934x; 3.0934x over previous
#include <cuda_runtime.h>
#include <cuda_bf16.h>

#define H       1024
#define NEXP    4
#define TPB     128                 // threads per block == rows per block
#define TILE_K  64
#define NTILE   (H / TILE_K)        // 16
#define TK4     (TILE_K / 4)        // 16 float4 per row-tile
#define XSTR    (TK4 + 1)           // padded float4 stride -> conflict-free LDS

// dynamic smem: [ wt: H float4 | xs: 2 * TPB * XSTR float4 ]
#define SMEM_BYTES ((H + 2 * TPB * XSTR) * (int)sizeof(float4))

__global__ __launch_bounds__(TPB) void moe_gate_kernel(
    const float* __restrict__ x,      // [N, 1024]
    const float* __restrict__ w,      // [4, 1024]
    float* __restrict__ out,          // [2N idx | 2N wgt | 1 aux] fp32
    int nrows)
{
    extern __shared__ float4 smem[];
    float4* wt = smem;                 // wt[k] = {w0[k], w1[k], w2[k], w3[k]}
    float4* xs = smem + H;             // double-buffered x tile

    const int tid  = threadIdx.x;
    const int wi   = tid >> 5;
    const int lane = tid & 31;

    // One-time: transpose weight into smem (16 KB), broadcast-friendly.
    for (int k = tid; k < H; k += TPB)
        wt[k] = make_float4(w[k], w[H + k], w[2 * H + k], w[3 * H + k]);

    const size_t row = (size_t)blockIdx.x * TPB + tid;
    const float* xblk = x + (size_t)blockIdx.x * TPB * H;

    // cp.async tile loader: warp wi covers rows [wi*32, wi*32+32);
    // each iter loads 2 rows (16 lanes x 16B = 256B contiguous per row).
    const int lrow2 = (lane >> 4);     // 0/1: which of the 2 rows
    const int lcol  = lane & 15;       // float4 column within 64-float tile

    float a0 = 0.f, a1 = 0.f, a2 = 0.f, a3 = 0.f;

    // ---- prologue: issue tile 0 ----
    {
        const float* src_base = xblk + 0 * TILE_K;
        float4* dstbuf = xs;           // buf 0
        #pragma unroll
        for (int it = 0; it < 16; it++) {
            int r = wi * 32 + it * 2 + lrow2;
            const float* src = src_base + (size_t)r * H + lcol * 4;
            float4* dst = dstbuf + r * XSTR + lcol;
            unsigned sa = (unsigned)__cvta_generic_to_shared(dst);
            asm volatile("cp.async.cg.shared.global [%0], [%1], 16;" :: "r"(sa), "l"(src));
        }
        asm volatile("cp.async.commit_group;" ::: "memory");
    }

    for (int t = 0; t < NTILE; t++) {
        if (t + 1 < NTILE) {
            // issue tile t+1 into the other buffer
            const float* src_base = xblk + (t + 1) * TILE_K;
            float4* dstbuf = xs + ((t + 1) & 1) * (TPB * XSTR);
            #pragma unroll
            for (int it = 0; it < 16; it++) {
                int r = wi * 32 + it * 2 + lrow2;
                const float* src = src_base + (size_t)r * H + lcol * 4;
                float4* dst = dstbuf + r * XSTR + lcol;
                unsigned sa = (unsigned)__cvta_generic_to_shared(dst);
                asm volatile("cp.async.cg.shared.global [%0], [%1], 16;" :: "r"(sa), "l"(src));
            }
            asm volatile("cp.async.commit_group;" ::: "memory");
            asm volatile("cp.async.wait_group 1;" ::: "memory");
        } else {
            asm volatile("cp.async.wait_group 0;" ::: "memory");
        }
        __syncthreads();   // tile t ready (also guards wt on t==0)

        // ---- compute tile t: 4 serial ascending fmaf chains (bit-exact) ----
        const float4* xrow = xs + (t & 1) * (TPB * XSTR) + tid * XSTR;
        const float4* wk   = wt + t * TILE_K;
        #pragma unroll
        for (int k4 = 0; k4 < TK4; k4++) {
            float4 v  = xrow[k4];                  // conflict-free (XSTR pad)
            float4 w0 = wk[k4 * 4 + 0];            // warp-uniform broadcast
            a0 = fmaf(v.x, w0.x, a0); a1 = fmaf(v.x, w0.y, a1);
            a2 = fmaf(v.x, w0.z, a2); a3 = fmaf(v.x, w0.w, a3);
            float4 w1 = wk[k4 * 4 + 1];
            a0 = fmaf(v.y, w1.x, a0); a1 = fmaf(v.y, w1.y, a1);
            a2 = fmaf(v.y, w1.z, a2); a3 = fmaf(v.y, w1.w, a3);
            float4 w2 = wk[k4 * 4 + 2];
            a0 = fmaf(v.z, w2.x, a0); a1 = fmaf(v.z, w2.y, a1);
            a2 = fmaf(v.z, w2.z, a2); a3 = fmaf(v.z, w2.w, a3);
            float4 w3 = wk[k4 * 4 + 3];
            a0 = fmaf(v.w, w3.x, a0); a1 = fmaf(v.w, w3.y, a1);
            a2 = fmaf(v.w, w3.z, a2); a3 = fmaf(v.w, w3.w, a3);
        }
        __syncthreads();   // protect buffer reuse by the next issue
    }

    if (row < (size_t)nrows) {
        float lg[NEXP] = {a0, a1, a2, a3};
        float m = lg[0];
        #pragma unroll
        for (int k = 1; k < NEXP; k++) m = fmaxf(m, lg[k]);

        // Validated reference-softmax emulation (R5/R8): accurate exp,
        // sequential fp32 sum, rn division, flush denormal scores to 0.
        float q[NEXP];
        #pragma unroll
        for (int k = 0; k < NEXP; k++)
            q[k] = (float)exp((double)(lg[k] - m));
        float sum = ((q[0] + q[1]) + q[2]) + q[3];

        unsigned kb[NEXP];
        float sc[NEXP];
        #pragma unroll
        for (int k = 0; k < NEXP; k++) {
            float s = __fdiv_rn(q[k], sum);
            unsigned b = __float_as_uint(s);
            if (b < 0x00800000u) { b = 0u; s = 0.0f; }
            kb[k] = b; sc[k] = s;
        }

        // top-2 by bit pattern; strict '>' => lowest index wins ties
        int i0 = 0;
        #pragma unroll
        for (int k = 1; k < NEXP; k++) if (kb[k] > kb[i0]) i0 = k;
        int i1 = -1;
        #pragma unroll
        for (int k = 0; k < NEXP; k++) {
            if (k == i0) continue;
            if (i1 < 0 || kb[k] > kb[i1]) i1 = k;
        }

        float2* oidx = reinterpret_cast<float2*>(out);
        float2* owgt = reinterpret_cast<float2*>(out + 2 * (size_t)nrows);
        oidx[row] = make_float2((float)i0, (float)i1);
        owgt[row] = make_float2(sc[i0], sc[i1]);

        if (row == 0)
            out[4 * (size_t)nrows] = 0.01f;   // aux_loss == ALPHA analytically
    }
}

extern "C" void kernel_launch(void* const* d_in, const int* in_sizes, int n_in,
                              void* d_out, int out_size)
{
    const float* x = (const float*)d_in[0];   // hidden_states [8,4096,1024] fp32
    const float* w = (const float*)d_in[1];   // weight [4,1024] fp32
    float* out = (float*)d_out;

    int nrows = in_sizes[0] / H;              // 32768
    int blocks = (nrows + TPB - 1) / TPB;     // 256

    cudaFuncSetAttribute(moe_gate_kernel,
                         cudaFuncAttributeMaxDynamicSharedMemorySize, SMEM_BYTES);
    moe_gate_kernel<<<blocks, TPB, SMEM_BYTES>>>(x, w, out, nrows);
}

// round 10
// speedup vs baseline: 3.2081x; 1.0371x over previous
#include <cuda_runtime.h>
#include <cuda_bf16.h>

#define H       1024
#define NEXP    4
#define TPB     128                 // 4 warps; rows per block
#define TILE_K  32
#define NTILE   (H / TILE_K)        // 32
#define TK4     (TILE_K / 4)        // 8 float4 per row-tile
#define XSTR    (TK4 + 1)           // 9 float4 stride -> conflict-free LDS.128
#define STAGES  4                   // 3 tiles in flight per warp

// dynamic smem: [ wt: H float4 | xs: STAGES * TPB * XSTR float4 ]
#define SMEM_BYTES ((H + STAGES * TPB * XSTR) * (int)sizeof(float4))

__device__ __forceinline__ void issue_tile(const float* __restrict__ xblk,
                                           float4* __restrict__ xslot,
                                           int wi, int lane, int t)
{
    // warp wi loads rows [wi*32, wi*32+32), TILE_K floats each.
    // per iter: 4 rows x 8 lanes x 16B = 4 contiguous 128B segments.
    const int rr = lane >> 3;      // 0..3 row-in-group
    const int c  = lane & 7;       // 0..7 float4 column
    const float* src0 = xblk + t * TILE_K + c * 4;
#pragma unroll
    for (int it = 0; it < 8; it++) {
        int r = wi * 32 + it * 4 + rr;
        const float* src = src0 + (size_t)r * H;
        float4* dst = xslot + r * XSTR + c;
        unsigned sa = (unsigned)__cvta_generic_to_shared(dst);
        asm volatile("cp.async.cg.shared.global [%0], [%1], 16;" :: "r"(sa), "l"(src));
    }
}

__global__ __launch_bounds__(TPB) void moe_gate_kernel(
    const float* __restrict__ x,      // [N, 1024]
    const float* __restrict__ w,      // [4, 1024]
    float* __restrict__ out,          // [2N idx | 2N wgt | 1 aux] fp32
    int nrows)
{
    extern __shared__ float4 smem[];
    float4* wt = smem;                          // wt[k] = {w0,w1,w2,w3}[k]
    float4* xs = smem + H;                      // STAGES slots

    const int tid  = threadIdx.x;
    const int wi   = tid >> 5;
    const int lane = tid & 31;
    const float* xblk = x + (size_t)blockIdx.x * TPB * H;

    // prologue: issue first STAGES-1 tiles (per-warp, independent)
#pragma unroll
    for (int p = 0; p < STAGES - 1; p++) {
        issue_tile(xblk, xs + p * (TPB * XSTR), wi, lane, p);
        asm volatile("cp.async.commit_group;" ::: "memory");
    }

    // weight transpose into smem (only block-wide dependency)
    for (int k = tid; k < H; k += TPB)
        wt[k] = make_float4(w[k], w[H + k], w[2 * H + k], w[3 * H + k]);
    __syncthreads();

    float a0 = 0.f, a1 = 0.f, a2 = 0.f, a3 = 0.f;

    for (int t = 0; t < NTILE; t++) {
        // oldest of the <=3 pending groups (tile t) is complete
        asm volatile("cp.async.wait_group 2;" ::: "memory");
        __syncwarp();   // make lane-mates' staged rows visible

        const float4* xrow = xs + (t & (STAGES - 1)) * (TPB * XSTR) + tid * XSTR;
        const float4* wk   = wt + t * TILE_K;
#pragma unroll
        for (int k4 = 0; k4 < TK4; k4++) {
            float4 v  = xrow[k4];                 // conflict-free via XSTR pad
            float4 w0 = wk[k4 * 4 + 0];           // warp-uniform broadcasts
            a0 = fmaf(v.x, w0.x, a0); a1 = fmaf(v.x, w0.y, a1);
            a2 = fmaf(v.x, w0.z, a2); a3 = fmaf(v.x, w0.w, a3);
            float4 w1 = wk[k4 * 4 + 1];
            a0 = fmaf(v.y, w1.x, a0); a1 = fmaf(v.y, w1.y, a1);
            a2 = fmaf(v.y, w1.z, a2); a3 = fmaf(v.y, w1.w, a3);
            float4 w2 = wk[k4 * 4 + 2];
            a0 = fmaf(v.z, w2.x, a0); a1 = fmaf(v.z, w2.y, a1);
            a2 = fmaf(v.z, w2.z, a2); a3 = fmaf(v.z, w2.w, a3);
            float4 w3 = wk[k4 * 4 + 3];
            a0 = fmaf(v.w, w3.x, a0); a1 = fmaf(v.w, w3.y, a1);
            a2 = fmaf(v.w, w3.z, a2); a3 = fmaf(v.w, w3.w, a3);
        }

        // refill the slot just freed (tile t-1's slot) with tile t+3.
        // The __syncwarp() above orders last iteration's reads before
        // this overwrite. Always commit (possibly-empty group) so
        // wait_group 2 stays exact at the tail.
        int tn = t + STAGES - 1;
        if (tn < NTILE)
            issue_tile(xblk, xs + (tn & (STAGES - 1)) * (TPB * XSTR), wi, lane, tn);
        asm volatile("cp.async.commit_group;" ::: "memory");
    }

    const size_t row = (size_t)blockIdx.x * TPB + tid;
    if (row < (size_t)nrows) {
        float lg[NEXP] = {a0, a1, a2, a3};
        float m = lg[0];
        #pragma unroll
        for (int k = 1; k < NEXP; k++) m = fmaxf(m, lg[k]);

        // Frozen reference-softmax contract (validated R5/R8): accurate
        // exp, sequential fp32 sum, rn division, flush denormals to 0.
        float q[NEXP];
        #pragma unroll
        for (int k = 0; k < NEXP; k++)
            q[k] = (float)exp((double)(lg[k] - m));
        float sum = ((q[0] + q[1]) + q[2]) + q[3];

        unsigned kb[NEXP];
        float sc[NEXP];
        #pragma unroll
        for (int k = 0; k < NEXP; k++) {
            float s = __fdiv_rn(q[k], sum);
            unsigned b = __float_as_uint(s);
            if (b < 0x00800000u) { b = 0u; s = 0.0f; }
            kb[k] = b; sc[k] = s;
        }

        int i0 = 0;
        #pragma unroll
        for (int k = 1; k < NEXP; k++) if (kb[k] > kb[i0]) i0 = k;
        int i1 = -1;
        #pragma unroll
        for (int k = 0; k < NEXP; k++) {
            if (k == i0) continue;
            if (i1 < 0 || kb[k] > kb[i1]) i1 = k;
        }

        float2* oidx = reinterpret_cast<float2*>(out);
        float2* owgt = reinterpret_cast<float2*>(out + 2 * (size_t)nrows);
        oidx[row] = make_float2((float)i0, (float)i1);
        owgt[row] = make_float2(sc[i0], sc[i1]);

        if (row == 0)
            out[4 * (size_t)nrows] = 0.01f;   // aux_loss == ALPHA analytically
    }
}

extern "C" void kernel_launch(void* const* d_in, const int* in_sizes, int n_in,
                              void* d_out, int out_size)
{
    const float* x = (const float*)d_in[0];   // hidden_states [8,4096,1024] fp32
    const float* w = (const float*)d_in[1];   // weight [4,1024] fp32
    float* out = (float*)d_out;

    int nrows = in_sizes[0] / H;              // 32768
    int blocks = (nrows + TPB - 1) / TPB;     // 256

    cudaFuncSetAttribute(moe_gate_kernel,
                         cudaFuncAttributeMaxDynamicSharedMemorySize, SMEM_BYTES);
    moe_gate_kernel<<<blocks, TPB, SMEM_BYTES>>>(x, w, out, nrows);
}